// round 14
// baseline (speedup 1.0000x reference)
#include <cuda_runtime.h>
#include <cuda_bf16.h>
#include <math.h>
#include <stdint.h>

// ---------------- problem constants ----------------
#define BB   2
#define SS   2048
#define HH   1024
#define NHH  16
#define HDD  64
#define LL   8
#define VV   32000
#define II   2730
#define MM   (BB*SS)

// ---------------- device scratch ----------------
__device__ float g_x  [MM*HH];
__device__ float g_qkv[(size_t)MM*3072];
__device__ float g_q2 [MM*HH];
__device__ float g_k2 [MM*HH];
__device__ float g_gu [(size_t)MM*5632];

// bf16 split buffers (A3 = [hi|lo|hi], B3 = [hi|hi|lo] along K)
__device__ __nv_bfloat16 g_a3[(size_t)MM*3072];
__device__ __nv_bfloat16 g_g3[(size_t)MM*8192];
__device__ __nv_bfloat16 g_b3[(size_t)5632*3072];
__device__ __nv_bfloat16 g_e3[(size_t)VV*3072];

// ---------------- embedding gather ----------------
__global__ void embed_kernel(const int* __restrict__ ids,
                             const float* __restrict__ emb,
                             float* __restrict__ x)
{
    int idx = blockIdx.x * blockDim.x + threadIdx.x;
    if (idx >= MM*HH) return;
    int m = idx >> 10;
    int d = idx & 1023;
    x[idx] = emb[(size_t)ids[m] * HH + d];
}

// ---------------- layernorm fused with bf16 split: writes A3 [hi|lo|hi] ----------------
__global__ void ln_split_kernel(const float* __restrict__ x,
                                const float* __restrict__ w,
                                const float* __restrict__ b,
                                __nv_bfloat16* __restrict__ a3)
{
    int row = blockIdx.x;
    const float* xr = x + (size_t)row * HH;
    float v[4], s = 0.f, sq = 0.f;
#pragma unroll
    for (int i = 0; i < 4; i++) {
        v[i] = xr[threadIdx.x + i*256];
        s  += v[i];
        sq += v[i]*v[i];
    }
    __shared__ float rs[8], rq[8];
    int lane = threadIdx.x & 31, wid = threadIdx.x >> 5;
#pragma unroll
    for (int off = 16; off > 0; off >>= 1) {
        s  += __shfl_xor_sync(0xffffffffu, s,  off);
        sq += __shfl_xor_sync(0xffffffffu, sq, off);
    }
    if (lane == 0) { rs[wid] = s; rq[wid] = sq; }
    __syncthreads();
    if (threadIdx.x == 0) {
        float ts = 0.f, tq = 0.f;
        for (int i = 0; i < 8; i++) { ts += rs[i]; tq += rq[i]; }
        rs[0] = ts; rq[0] = tq;
    }
    __syncthreads();
    float mu  = rs[0] * (1.f/HH);
    float var = rq[0] * (1.f/HH) - mu*mu;
    float inv = rsqrtf(var + 1e-5f);
    __nv_bfloat16* arow = a3 + (size_t)row * 3072;
#pragma unroll
    for (int i = 0; i < 4; i++) {
        int d = threadIdx.x + i*256;
        float y = (v[i] - mu) * inv * w[d] + b[d];
        __nv_bfloat16 h = __float2bfloat16(y);
        __nv_bfloat16 l = __float2bfloat16(y - __bfloat162float(h));
        arow[d]        = h;
        arow[1024 + d] = l;
        arow[2048 + d] = h;
    }
}

// ---------------- RoPE v2 (proven correct), reads fused qkv ----------------
__global__ __launch_bounds__(512)
void rope2_kernel(const float* __restrict__ qkv,
                  float* __restrict__ qout, float* __restrict__ kout)
{
    const int m = blockIdx.x;
    const int t = threadIdx.x;
    const int head = t >> 5;
    const int i    = t & 31;
    const int s    = m % SS;

    const float LOG1E4_OVER_32 = 0.28782313662425f;
    float invf = expf(-(float)i * LOG1E4_OVER_32);
    float ang  = (float)s * invf;
    float c  = cosf(ang);
    float sn = sinf(ang);

    size_t inb  = (size_t)m * 3072 + head * HDD + i;
    size_t outb = (size_t)m * HH   + head * HDD + i;
    float qa = qkv[inb], qb = qkv[inb + 32];
    qout[outb]      = fmaf(qa, c, -qb * sn);
    qout[outb + 32] = fmaf(qb, c,  qa * sn);
    float ka = qkv[inb + 1024], kb = qkv[inb + 1024 + 32];
    kout[outb]      = fmaf(ka, c, -kb * sn);
    kout[outb + 32] = fmaf(kb, c,  ka * sn);
}

// ---------------- SiLU(gate)*up fused with bf16 split: writes G3 [hi|lo|hi] ----------------
__global__ void silu_split_kernel(const float* __restrict__ gu,
                                  __nv_bfloat16* __restrict__ g3)
{
    int c = blockIdx.x * blockDim.x + threadIdx.x;
    int m = blockIdx.y;
    if (c >= II) return;
    size_t a = (size_t)m * 5632 + c;
    float x = gu[a];
    float y = x / (1.f + expf(-x)) * gu[a + 2816];
    __nv_bfloat16 h = __float2bfloat16(y);
    __nv_bfloat16 l = __float2bfloat16(y - __bfloat162float(h));
    size_t base = (size_t)m * 8192;
    g3[base + c]          = h;
    g3[base + 2730 + c]   = l;
    g3[base + 5460 + c]   = h;
    if (c < 2) g3[base + 8190 + c] = __float2bfloat16(0.f);
}

// ---------------- weight conversions ----------------
// combined qkv: rows [0,1024)=q, [1024,2048)=k, [2048,3072)=v  (K=1024, ld3=3072)
__global__ void split_w_qkv(const float* __restrict__ qw, const float* __restrict__ kw,
                            const float* __restrict__ vw, __nv_bfloat16* __restrict__ B3)
{
    int idx = blockIdx.x*256 + threadIdx.x;
    if (idx >= 3072*1024) return;
    int n = idx >> 10, k = idx & 1023;
    const float* W = (n < 1024) ? qw : ((n < 2048) ? kw : vw);
    int nn = n & 1023;
    float x = W[(size_t)k*1024 + nn];
    __nv_bfloat16 h = __float2bfloat16(x);
    __nv_bfloat16 l = __float2bfloat16(x - __bfloat162float(h));
    size_t base = (size_t)n*3072;
    B3[base + k]        = h;
    B3[base + 1024 + k] = h;
    B3[base + 2048 + k] = l;
}

// combined gate+up: rows [0,2816)=gate, [2816,5632)=up (K=1024, N=2730 each, ld3=3072)
__global__ void split_w_gu(const float* __restrict__ gw, const float* __restrict__ uw,
                           __nv_bfloat16* __restrict__ B3)
{
    int idx = blockIdx.x*256 + threadIdx.x;
    if (idx >= 5632*1024) return;
    int n = idx >> 10, k = idx & 1023;
    const float* W = (n < 2816) ? gw : uw;
    int nn = (n < 2816) ? n : (n - 2816);
    float x = (nn < II) ? W[(size_t)k*II + nn] : 0.f;
    __nv_bfloat16 h = __float2bfloat16(x);
    __nv_bfloat16 l = __float2bfloat16(x - __bfloat162float(h));
    size_t base = (size_t)n*3072;
    B3[base + k]        = h;
    B3[base + 1024 + k] = h;
    B3[base + 2048 + k] = l;
}

// generic (o-proj, down)
__global__ void split_w(const float* __restrict__ W, int K, int N, int Npad,
                        __nv_bfloat16* __restrict__ B3, int ld3, int total)
{
    int idx = blockIdx.x*256 + threadIdx.x;
    if (idx >= total) return;
    int n = idx / K, k = idx - n*K;
    float x = (n < N) ? W[(size_t)k*N + n] : 0.f;
    __nv_bfloat16 h = __float2bfloat16(x);
    __nv_bfloat16 l = __float2bfloat16(x - __bfloat162float(h));
    size_t base = (size_t)n*ld3;
    B3[base + k]       = h;
    B3[base + K + k]   = h;
    B3[base + 2*K + k] = l;
    int pad = ld3 - 3*K;
    if (k < pad) B3[base + 3*K + k] = __float2bfloat16(0.f);
}

__global__ void split_emb(const float* __restrict__ E, __nv_bfloat16* __restrict__ E3)
{
    int idx = blockIdx.x*256 + threadIdx.x;
    if (idx >= VV*HH) return;
    int n = idx >> 10, k = idx & 1023;
    float x = E[idx];
    __nv_bfloat16 h = __float2bfloat16(x);
    __nv_bfloat16 l = __float2bfloat16(x - __bfloat162float(h));
    size_t base = (size_t)n*3072;
    E3[base + k]        = h;
    E3[base + 1024 + k] = h;
    E3[base + 2048 + k] = l;
}

// ---------------- tensor-core GEMM (R8-proven config, verbatim) ----------------
__device__ __forceinline__ unsigned swzoff(int row, int ch)
{
    return (unsigned)(row*64 + ((ch ^ ((row>>1)&3)) << 4));
}

__global__ __launch_bounds__(256)
void bgemm(const __nv_bfloat16* __restrict__ A3, int lda,
           const __nv_bfloat16* __restrict__ B3, int ldb,
           float* __restrict__ C, int ldc,
           int N, int K3, int ACC)
{
    __shared__ __align__(16) __nv_bfloat16 smA[3][128*32];
    __shared__ __align__(16) __nv_bfloat16 smB[3][128*32];

    const int tid  = threadIdx.x;
    const int lane = tid & 31, warp = tid >> 5;
    const int wm = warp >> 2, wn = warp & 3;
    const int bm = blockIdx.y * 128, bn = blockIdx.x * 128;

    const unsigned sA0 = (unsigned)__cvta_generic_to_shared(&smA[0][0]);
    const unsigned sB0 = (unsigned)__cvta_generic_to_shared(&smB[0][0]);

    float acc[4][4][4];
#pragma unroll
    for (int i = 0; i < 4; i++)
#pragma unroll
        for (int j = 0; j < 4; j++)
#pragma unroll
            for (int r = 0; r < 4; r++) acc[i][j][r] = 0.f;

    const int S = K3 >> 5;

    auto issue = [&](int s) {
        const int buf = s % 3;
        const int k0  = s << 5;
#pragma unroll
        for (int i = 0; i < 2; i++) {
            int idx = i*256 + tid;
            int row = idx >> 2, ch = idx & 3;
            unsigned so = (unsigned)(buf*8192) + swzoff(row, ch);
            const __nv_bfloat16* ga = A3 + (size_t)(bm+row)*lda + k0 + ch*8;
            asm volatile("cp.async.cg.shared.global [%0], [%1], 16;\n" :: "r"(sA0+so), "l"(ga));
            const __nv_bfloat16* gb = B3 + (size_t)(bn+row)*ldb + k0 + ch*8;
            asm volatile("cp.async.cg.shared.global [%0], [%1], 16;\n" :: "r"(sB0+so), "l"(gb));
        }
        asm volatile("cp.async.commit_group;\n" ::);
    };

    issue(0); issue(1);

    for (int s = 0; s < S; s++) {
        if (s + 1 < S) asm volatile("cp.async.wait_group 1;\n" ::);
        else           asm volatile("cp.async.wait_group 0;\n" ::);
        __syncthreads();
        if (s + 2 < S) issue(s + 2);

        const int buf = s % 3;
        const unsigned baseA = sA0 + (unsigned)(buf*8192);
        const unsigned baseB = sB0 + (unsigned)(buf*8192);
#pragma unroll
        for (int ks = 0; ks < 2; ks++) {
            const int c0 = ks*2;
            unsigned a[4][4], b[4][2];
#pragma unroll
            for (int mt = 0; mt < 4; mt++) {
                int row = wm*64 + mt*16 + (lane & 7) + ((lane >> 3) & 1)*8;
                int ch  = c0 + (lane >> 4);
                unsigned ad = baseA + swzoff(row, ch);
                asm volatile("ldmatrix.sync.aligned.m8n8.x4.shared.b16 {%0,%1,%2,%3}, [%4];"
                    : "=r"(a[mt][0]), "=r"(a[mt][1]), "=r"(a[mt][2]), "=r"(a[mt][3]) : "r"(ad));
            }
#pragma unroll
            for (int p = 0; p < 2; p++) {
                int row = wn*32 + p*16 + (lane & 7) + ((lane >> 4) & 1)*8;
                int ch  = c0 + ((lane >> 3) & 1);
                unsigned ad = baseB + swzoff(row, ch);
                unsigned r0, r1, r2, r3;
                asm volatile("ldmatrix.sync.aligned.m8n8.x4.shared.b16 {%0,%1,%2,%3}, [%4];"
                    : "=r"(r0), "=r"(r1), "=r"(r2), "=r"(r3) : "r"(ad));
                b[2*p][0] = r0; b[2*p][1] = r1; b[2*p+1][0] = r2; b[2*p+1][1] = r3;
            }
#pragma unroll
            for (int mt = 0; mt < 4; mt++)
#pragma unroll
                for (int nt = 0; nt < 4; nt++)
                    asm volatile("mma.sync.aligned.m16n8k16.row.col.f32.bf16.bf16.f32 "
                        "{%0,%1,%2,%3}, {%4,%5,%6,%7}, {%8,%9}, {%0,%1,%2,%3};"
                        : "+f"(acc[mt][nt][0]), "+f"(acc[mt][nt][1]),
                          "+f"(acc[mt][nt][2]), "+f"(acc[mt][nt][3])
                        : "r"(a[mt][0]), "r"(a[mt][1]), "r"(a[mt][2]), "r"(a[mt][3]),
                          "r"(b[nt][0]), "r"(b[nt][1]));
        }
    }

    // epilogue
#pragma unroll
    for (int mt = 0; mt < 4; mt++) {
        int grow = bm + wm*64 + mt*16 + (lane >> 2);
#pragma unroll
        for (int nt = 0; nt < 4; nt++) {
            int gcol = bn + wn*32 + nt*8 + 2*(lane & 3);
            if (gcol < N) {
                float2* p0 = (float2*)&C[(size_t)grow*ldc + gcol];
                float2* p1 = (float2*)&C[(size_t)(grow+8)*ldc + gcol];
                float2 v0 = make_float2(acc[mt][nt][0], acc[mt][nt][1]);
                float2 v1 = make_float2(acc[mt][nt][2], acc[mt][nt][3]);
                if (ACC) {
                    float2 o0 = *p0, o1 = *p1;
                    v0.x += o0.x; v0.y += o0.y; v1.x += o1.x; v1.y += o1.y;
                }
                *p0 = v0; *p1 = v1;
            }
        }
    }
}

// ---------------- flash attention; epilogue writes bf16 split A3 directly ----------------
__global__ __launch_bounds__(256)
void attn_kernel(const float* __restrict__ q, const float* __restrict__ k,
                 const float* __restrict__ v, int ldv, const int* __restrict__ ids,
                 __nv_bfloat16* __restrict__ a3)
{
    __shared__ __align__(16) float QT[64][65];
    __shared__ __align__(16) float KT[64][33];
    __shared__ __align__(16) float Ps[32][65];
    __shared__ __align__(16) float Vs[32][64];
    __shared__ float pads[32];

    const int b  = blockIdx.z, h = blockIdx.y, q0 = blockIdx.x * 64;
    const int tid = threadIdx.x;
    const int sx = tid & 15, sy = tid >> 4;
    const size_t hoff = (size_t)h * HDD;

    for (int i2 = tid; i2 < 64*64; i2 += 256) {
        int r = i2 >> 6, d = i2 & 63;
        QT[d][r] = q[((size_t)(b*SS + q0 + r))*HH + hoff + d];
    }
    float m[4], l[4], o[4][4];
#pragma unroll
    for (int i = 0; i < 4; i++) {
        m[i] = -3e38f; l[i] = 0.f;
#pragma unroll
        for (int j = 0; j < 4; j++) o[i][j] = 0.f;
    }
    __syncthreads();

    const int nk = q0 + 64;
    for (int c0 = 0; c0 < nk; c0 += 32) {
        for (int i2 = tid; i2 < 32*64; i2 += 256) {
            int c = i2 >> 6, d = i2 & 63;
            KT[d][c] = k[((size_t)(b*SS + c0 + c))*HH + hoff + d];
        }
        if (tid < 32)
            pads[tid] = (ids[b*SS + c0 + tid] != 0) ? 0.f : -10000.f;
        __syncthreads();

        float sv[4][2];
#pragma unroll
        for (int i = 0; i < 4; i++) { sv[i][0] = 0.f; sv[i][1] = 0.f; }
#pragma unroll 4
        for (int d = 0; d < 64; d++) {
            float a0 = QT[d][sy*4+0], a1 = QT[d][sy*4+1];
            float a2 = QT[d][sy*4+2], a3v = QT[d][sy*4+3];
            float b0 = KT[d][sx*2+0], b1 = KT[d][sx*2+1];
            sv[0][0] += a0*b0; sv[0][1] += a0*b1;
            sv[1][0] += a1*b0; sv[1][1] += a1*b1;
            sv[2][0] += a2*b0; sv[2][1] += a2*b1;
            sv[3][0] += a3v*b0; sv[3][1] += a3v*b1;
        }

        float corr[4];
#pragma unroll
        for (int i = 0; i < 4; i++) {
            int qrow = q0 + sy*4 + i;
#pragma unroll
            for (int j = 0; j < 2; j++) {
                int cc = c0 + sx*2 + j;
                float s_ = sv[i][j]*0.125f + pads[sx*2+j];
                if (cc > qrow) s_ = -3e38f;
                sv[i][j] = s_;
            }
            float tmax = fmaxf(sv[i][0], sv[i][1]);
#pragma unroll
            for (int off = 8; off > 0; off >>= 1)
                tmax = fmaxf(tmax, __shfl_xor_sync(0xffffffffu, tmax, off));
            float mn = fmaxf(m[i], tmax);
            corr[i] = expf(m[i] - mn);
            m[i] = mn;
            float p0 = expf(sv[i][0] - mn);
            float p1 = expf(sv[i][1] - mn);
            float rs = p0 + p1;
#pragma unroll
            for (int off = 8; off > 0; off >>= 1)
                rs += __shfl_xor_sync(0xffffffffu, rs, off);
            l[i] = l[i]*corr[i] + rs;
            Ps[sx*2+0][sy*4+i] = p0;
            Ps[sx*2+1][sy*4+i] = p1;
#pragma unroll
            for (int j = 0; j < 4; j++) o[i][j] *= corr[i];
        }
        __syncthreads();

        for (int i2 = tid; i2 < 32*64; i2 += 256) {
            int c = i2 >> 6, d = i2 & 63;
            Vs[c][d] = v[((size_t)(b*SS + c0 + c))*ldv + hoff + d];
        }
        __syncthreads();

#pragma unroll 4
        for (int c = 0; c < 32; c++) {
            float p0 = Ps[c][sy*4+0], p1 = Ps[c][sy*4+1];
            float p2 = Ps[c][sy*4+2], p3 = Ps[c][sy*4+3];
            float4 vv = *(const float4*)&Vs[c][sx*4];
            o[0][0] += p0*vv.x; o[0][1] += p0*vv.y; o[0][2] += p0*vv.z; o[0][3] += p0*vv.w;
            o[1][0] += p1*vv.x; o[1][1] += p1*vv.y; o[1][2] += p1*vv.z; o[1][3] += p1*vv.w;
            o[2][0] += p2*vv.x; o[2][1] += p2*vv.y; o[2][2] += p2*vv.z; o[2][3] += p2*vv.w;
            o[3][0] += p3*vv.x; o[3][1] += p3*vv.y; o[3][2] += p3*vv.z; o[3][3] += p3*vv.w;
        }
        __syncthreads();
    }

#pragma unroll
    for (int i = 0; i < 4; i++) {
        float inv = 1.f / l[i];
        size_t arow = (size_t)(b*SS + q0 + sy*4 + i) * 3072 + hoff + sx*4;
#pragma unroll
        for (int e = 0; e < 4; e++) {
            float y = o[i][e] * inv;
            __nv_bfloat16 hh = __float2bfloat16(y);
            __nv_bfloat16 ll = __float2bfloat16(y - __bfloat162float(hh));
            a3[arow + e]        = hh;
            a3[arow + 1024 + e] = ll;
            a3[arow + 2048 + e] = hh;
        }
    }
}

// ---------------- launch ----------------
extern "C" void kernel_launch(void* const* d_in, const int* in_sizes, int n_in,
                              void* d_out, int out_size)
{
    if (n_in != 15) return;
    const int expect[15] = {
        MM, VV*HH,
        LL*HH*HH, LL*HH*HH, LL*HH*HH, LL*HH*HH,
        LL*HH*II, LL*HH*II, LL*II*HH,
        LL*HH, LL*HH, LL*HH, LL*HH,
        HH, HH
    };
    for (int i = 0; i < 15; i++)
        if (in_sizes[i] != expect[i]) return;

    const int*   ids    = (const int*)  d_in[0];
    const float* emb    = (const float*)d_in[1];
    const float* q_w    = (const float*)d_in[2];
    const float* k_w    = (const float*)d_in[3];
    const float* v_w    = (const float*)d_in[4];
    const float* o_w    = (const float*)d_in[5];
    const float* gate_w = (const float*)d_in[6];
    const float* up_w   = (const float*)d_in[7];
    const float* down_w = (const float*)d_in[8];
    const float* ln1_w  = (const float*)d_in[9];
    const float* ln1_b  = (const float*)d_in[10];
    const float* ln2_w  = (const float*)d_in[11];
    const float* ln2_b  = (const float*)d_in[12];
    const float* lnf_w  = (const float*)d_in[13];
    const float* lnf_b  = (const float*)d_in[14];
    float* out = (float*)d_out;

    float *px, *pqkv, *pq2, *pk2, *pgu;
    __nv_bfloat16 *pa3, *pg3, *pb3, *pe3;
    cudaGetSymbolAddress((void**)&px,   g_x);
    cudaGetSymbolAddress((void**)&pqkv, g_qkv);
    cudaGetSymbolAddress((void**)&pq2,  g_q2);
    cudaGetSymbolAddress((void**)&pk2,  g_k2);
    cudaGetSymbolAddress((void**)&pgu,  g_gu);
    cudaGetSymbolAddress((void**)&pa3,  g_a3);
    cudaGetSymbolAddress((void**)&pg3,  g_g3);
    cudaGetSymbolAddress((void**)&pb3,  g_b3);
    cudaGetSymbolAddress((void**)&pe3,  g_e3);

    embed_kernel<<<(MM*HH + 255)/256, 256>>>(ids, emb, px);        // launch 0
    split_emb<<<(VV*HH + 255)/256, 256>>>(emb, pe3);               // launch 1

    const int TWQ  = HH*HH;
    const int TWD  = HH*II;

    dim3 go(8, 32);                // N=1024, 256 CTAs -> 1 wave @2 CTA/SM
    dim3 ggu(44, 32);              // N=5632
    dim3 glog(250, 32);            // N=32000
    dim3 gattn(SS/64, NHH, BB);
    dim3 gsilu((II + 255)/256, MM);

    for (int l = 0; l < LL; l++) {
        const float* qw = q_w    + (size_t)l*HH*HH;
        const float* kw = k_w    + (size_t)l*HH*HH;
        const float* vw = v_w    + (size_t)l*HH*HH;
        const float* ow = o_w    + (size_t)l*HH*HH;
        const float* gw = gate_w + (size_t)l*HH*II;
        const float* uw = up_w   + (size_t)l*HH*II;
        const float* dw = down_w + (size_t)l*II*HH;

        ln_split_kernel<<<MM, 256>>>(px, ln1_w + l*HH, ln1_b + l*HH, pa3);   // l0: launch 2
        split_w_qkv<<<(3072*1024+255)/256, 256>>>(qw, kw, vw, pb3);          // l0: launch 3

        // unfused QKV GEMMs: 256 CTAs each = single wave at 2 CTA/SM
        bgemm<<<go, 256>>>(pa3, 3072, pb3,                     3072, pqkv,        3072, HH, 3072, 0); // launch 4
        bgemm<<<go, 256>>>(pa3, 3072, pb3 + (size_t)1024*3072, 3072, pqkv + 1024, 3072, HH, 3072, 0); // launch 5 <- profiled
        bgemm<<<go, 256>>>(pa3, 3072, pb3 + (size_t)2048*3072, 3072, pqkv + 2048, 3072, HH, 3072, 0);

        rope2_kernel<<<MM, 512>>>(pqkv, pq2, pk2);
        attn_kernel<<<gattn, 256>>>(pq2, pk2, pqkv + 2048, 3072, ids, pa3);

        split_w<<<(TWQ+255)/256, 256>>>(ow, HH, HH, HH, pb3, 3072, TWQ);
        bgemm<<<go, 256>>>(pa3, 3072, pb3, 3072, px, HH, HH, 3072, 1);

        ln_split_kernel<<<MM, 256>>>(px, ln2_w + l*HH, ln2_b + l*HH, pa3);

        split_w_gu<<<(5632*1024+255)/256, 256>>>(gw, uw, pb3);
        bgemm<<<ggu, 256>>>(pa3, 3072, pb3, 3072, pgu, 5632, 5632, 3072, 0);

        silu_split_kernel<<<gsilu, 256>>>(pgu, pg3);

        split_w<<<(TWD+255)/256, 256>>>(dw, II, HH, HH, pb3, 8192, TWD);
        bgemm<<<go, 256>>>(pg3, 8192, pb3, 8192, px, HH, HH, 8192, 1);
    }

    ln_split_kernel<<<MM, 256>>>(px, lnf_w, lnf_b, pa3);
    bgemm<<<glog, 256>>>(pa3, 3072, pe3, 3072, out, VV, VV, 3072, 0);
}

// round 15
// speedup vs baseline: 1.0645x; 1.0645x over previous
#include <cuda_runtime.h>
#include <cuda_bf16.h>
#include <math.h>
#include <stdint.h>

// ---------------- problem constants ----------------
#define BB   2
#define SS   2048
#define HH   1024
#define NHH  16
#define HDD  64
#define LL   8
#define VV   32000
#define II   2730
#define MM   (BB*SS)

// ---------------- device scratch ----------------
__device__ float g_x  [MM*HH];
__device__ float g_qkv[(size_t)MM*3072];
__device__ float g_q2 [MM*HH];
__device__ float g_k2 [MM*HH];
__device__ float g_gu [(size_t)MM*5632];

// bf16 split buffers (A3 = [hi|lo|hi], B3 = [hi|hi|lo] along K)
__device__ __nv_bfloat16 g_a3[(size_t)MM*3072];
__device__ __nv_bfloat16 g_g3[(size_t)MM*8192];
__device__ __nv_bfloat16 g_b3[(size_t)5632*3072];
__device__ __nv_bfloat16 g_e3[(size_t)VV*3072];

// ---------------- embedding gather ----------------
__global__ void embed_kernel(const int* __restrict__ ids,
                             const float* __restrict__ emb,
                             float* __restrict__ x)
{
    int idx = blockIdx.x * blockDim.x + threadIdx.x;
    if (idx >= MM*HH) return;
    int m = idx >> 10;
    int d = idx & 1023;
    x[idx] = emb[(size_t)ids[m] * HH + d];
}

// ---------------- layernorm fused with bf16 split: writes A3 [hi|lo|hi] ----------------
__global__ void ln_split_kernel(const float* __restrict__ x,
                                const float* __restrict__ w,
                                const float* __restrict__ b,
                                __nv_bfloat16* __restrict__ a3)
{
    int row = blockIdx.x;
    const float* xr = x + (size_t)row * HH;
    float v[4], s = 0.f, sq = 0.f;
#pragma unroll
    for (int i = 0; i < 4; i++) {
        v[i] = xr[threadIdx.x + i*256];
        s  += v[i];
        sq += v[i]*v[i];
    }
    __shared__ float rs[8], rq[8];
    int lane = threadIdx.x & 31, wid = threadIdx.x >> 5;
#pragma unroll
    for (int off = 16; off > 0; off >>= 1) {
        s  += __shfl_xor_sync(0xffffffffu, s,  off);
        sq += __shfl_xor_sync(0xffffffffu, sq, off);
    }
    if (lane == 0) { rs[wid] = s; rq[wid] = sq; }
    __syncthreads();
    if (threadIdx.x == 0) {
        float ts = 0.f, tq = 0.f;
        for (int i = 0; i < 8; i++) { ts += rs[i]; tq += rq[i]; }
        rs[0] = ts; rq[0] = tq;
    }
    __syncthreads();
    float mu  = rs[0] * (1.f/HH);
    float var = rq[0] * (1.f/HH) - mu*mu;
    float inv = rsqrtf(var + 1e-5f);
    __nv_bfloat16* arow = a3 + (size_t)row * 3072;
#pragma unroll
    for (int i = 0; i < 4; i++) {
        int d = threadIdx.x + i*256;
        float y = (v[i] - mu) * inv * w[d] + b[d];
        __nv_bfloat16 h = __float2bfloat16(y);
        __nv_bfloat16 l = __float2bfloat16(y - __bfloat162float(h));
        arow[d]        = h;
        arow[1024 + d] = l;
        arow[2048 + d] = h;
    }
}

// ---------------- RoPE v2 (proven correct), reads fused qkv ----------------
__global__ __launch_bounds__(512)
void rope2_kernel(const float* __restrict__ qkv,
                  float* __restrict__ qout, float* __restrict__ kout)
{
    const int m = blockIdx.x;
    const int t = threadIdx.x;
    const int head = t >> 5;
    const int i    = t & 31;
    const int s    = m % SS;

    const float LOG1E4_OVER_32 = 0.28782313662425f;
    float invf = expf(-(float)i * LOG1E4_OVER_32);
    float ang  = (float)s * invf;
    float c  = cosf(ang);
    float sn = sinf(ang);

    size_t inb  = (size_t)m * 3072 + head * HDD + i;
    size_t outb = (size_t)m * HH   + head * HDD + i;
    float qa = qkv[inb], qb = qkv[inb + 32];
    qout[outb]      = fmaf(qa, c, -qb * sn);
    qout[outb + 32] = fmaf(qb, c,  qa * sn);
    float ka = qkv[inb + 1024], kb = qkv[inb + 1024 + 32];
    kout[outb]      = fmaf(ka, c, -kb * sn);
    kout[outb + 32] = fmaf(kb, c,  ka * sn);
}

// ---------------- SiLU(gate)*up fused with bf16 split: writes G3 [hi|lo|hi] ----------------
__global__ void silu_split_kernel(const float* __restrict__ gu,
                                  __nv_bfloat16* __restrict__ g3)
{
    int c = blockIdx.x * blockDim.x + threadIdx.x;
    int m = blockIdx.y;
    if (c >= II) return;
    size_t a = (size_t)m * 5632 + c;
    float x = gu[a];
    float y = x / (1.f + expf(-x)) * gu[a + 2816];
    __nv_bfloat16 h = __float2bfloat16(y);
    __nv_bfloat16 l = __float2bfloat16(y - __bfloat162float(h));
    size_t base = (size_t)m * 8192;
    g3[base + c]          = h;
    g3[base + 2730 + c]   = l;
    g3[base + 5460 + c]   = h;
    if (c < 2) g3[base + 8190 + c] = __float2bfloat16(0.f);
}

// ---------------- weight conversions ----------------
__global__ void split_w_qkv(const float* __restrict__ qw, const float* __restrict__ kw,
                            const float* __restrict__ vw, __nv_bfloat16* __restrict__ B3)
{
    int idx = blockIdx.x*256 + threadIdx.x;
    if (idx >= 3072*1024) return;
    int n = idx >> 10, k = idx & 1023;
    const float* W = (n < 1024) ? qw : ((n < 2048) ? kw : vw);
    int nn = n & 1023;
    float x = W[(size_t)k*1024 + nn];
    __nv_bfloat16 h = __float2bfloat16(x);
    __nv_bfloat16 l = __float2bfloat16(x - __bfloat162float(h));
    size_t base = (size_t)n*3072;
    B3[base + k]        = h;
    B3[base + 1024 + k] = h;
    B3[base + 2048 + k] = l;
}

__global__ void split_w_gu(const float* __restrict__ gw, const float* __restrict__ uw,
                           __nv_bfloat16* __restrict__ B3)
{
    int idx = blockIdx.x*256 + threadIdx.x;
    if (idx >= 5632*1024) return;
    int n = idx >> 10, k = idx & 1023;
    const float* W = (n < 2816) ? gw : uw;
    int nn = (n < 2816) ? n : (n - 2816);
    float x = (nn < II) ? W[(size_t)k*II + nn] : 0.f;
    __nv_bfloat16 h = __float2bfloat16(x);
    __nv_bfloat16 l = __float2bfloat16(x - __bfloat162float(h));
    size_t base = (size_t)n*3072;
    B3[base + k]        = h;
    B3[base + 1024 + k] = h;
    B3[base + 2048 + k] = l;
}

__global__ void split_w(const float* __restrict__ W, int K, int N, int Npad,
                        __nv_bfloat16* __restrict__ B3, int ld3, int total)
{
    int idx = blockIdx.x*256 + threadIdx.x;
    if (idx >= total) return;
    int n = idx / K, k = idx - n*K;
    float x = (n < N) ? W[(size_t)k*N + n] : 0.f;
    __nv_bfloat16 h = __float2bfloat16(x);
    __nv_bfloat16 l = __float2bfloat16(x - __bfloat162float(h));
    size_t base = (size_t)n*ld3;
    B3[base + k]       = h;
    B3[base + K + k]   = h;
    B3[base + 2*K + k] = l;
    int pad = ld3 - 3*K;
    if (k < pad) B3[base + 3*K + k] = __float2bfloat16(0.f);
}

__global__ void split_emb(const float* __restrict__ E, __nv_bfloat16* __restrict__ E3)
{
    int idx = blockIdx.x*256 + threadIdx.x;
    if (idx >= VV*HH) return;
    int n = idx >> 10, k = idx & 1023;
    float x = E[idx];
    __nv_bfloat16 h = __float2bfloat16(x);
    __nv_bfloat16 l = __float2bfloat16(x - __bfloat162float(h));
    size_t base = (size_t)n*3072;
    E3[base + k]        = h;
    E3[base + 1024 + k] = h;
    E3[base + 2048 + k] = l;
}

// ---------------- tensor-core GEMM (R8-proven config, verbatim) ----------------
__device__ __forceinline__ unsigned swzoff(int row, int ch)
{
    return (unsigned)(row*64 + ((ch ^ ((row>>1)&3)) << 4));
}

__global__ __launch_bounds__(256)
void bgemm(const __nv_bfloat16* __restrict__ A3, int lda,
           const __nv_bfloat16* __restrict__ B3, int ldb,
           float* __restrict__ C, int ldc,
           int N, int K3, int ACC)
{
    __shared__ __align__(16) __nv_bfloat16 smA[3][128*32];
    __shared__ __align__(16) __nv_bfloat16 smB[3][128*32];

    const int tid  = threadIdx.x;
    const int lane = tid & 31, warp = tid >> 5;
    const int wm = warp >> 2, wn = warp & 3;
    const int bm = blockIdx.y * 128, bn = blockIdx.x * 128;

    const unsigned sA0 = (unsigned)__cvta_generic_to_shared(&smA[0][0]);
    const unsigned sB0 = (unsigned)__cvta_generic_to_shared(&smB[0][0]);

    float acc[4][4][4];
#pragma unroll
    for (int i = 0; i < 4; i++)
#pragma unroll
        for (int j = 0; j < 4; j++)
#pragma unroll
            for (int r = 0; r < 4; r++) acc[i][j][r] = 0.f;

    const int S = K3 >> 5;

    auto issue = [&](int s) {
        const int buf = s % 3;
        const int k0  = s << 5;
#pragma unroll
        for (int i = 0; i < 2; i++) {
            int idx = i*256 + tid;
            int row = idx >> 2, ch = idx & 3;
            unsigned so = (unsigned)(buf*8192) + swzoff(row, ch);
            const __nv_bfloat16* ga = A3 + (size_t)(bm+row)*lda + k0 + ch*8;
            asm volatile("cp.async.cg.shared.global [%0], [%1], 16;\n" :: "r"(sA0+so), "l"(ga));
            const __nv_bfloat16* gb = B3 + (size_t)(bn+row)*ldb + k0 + ch*8;
            asm volatile("cp.async.cg.shared.global [%0], [%1], 16;\n" :: "r"(sB0+so), "l"(gb));
        }
        asm volatile("cp.async.commit_group;\n" ::);
    };

    issue(0); issue(1);

    for (int s = 0; s < S; s++) {
        if (s + 1 < S) asm volatile("cp.async.wait_group 1;\n" ::);
        else           asm volatile("cp.async.wait_group 0;\n" ::);
        __syncthreads();
        if (s + 2 < S) issue(s + 2);

        const int buf = s % 3;
        const unsigned baseA = sA0 + (unsigned)(buf*8192);
        const unsigned baseB = sB0 + (unsigned)(buf*8192);
#pragma unroll
        for (int ks = 0; ks < 2; ks++) {
            const int c0 = ks*2;
            unsigned a[4][4], b[4][2];
#pragma unroll
            for (int mt = 0; mt < 4; mt++) {
                int row = wm*64 + mt*16 + (lane & 7) + ((lane >> 3) & 1)*8;
                int ch  = c0 + (lane >> 4);
                unsigned ad = baseA + swzoff(row, ch);
                asm volatile("ldmatrix.sync.aligned.m8n8.x4.shared.b16 {%0,%1,%2,%3}, [%4];"
                    : "=r"(a[mt][0]), "=r"(a[mt][1]), "=r"(a[mt][2]), "=r"(a[mt][3]) : "r"(ad));
            }
#pragma unroll
            for (int p = 0; p < 2; p++) {
                int row = wn*32 + p*16 + (lane & 7) + ((lane >> 4) & 1)*8;
                int ch  = c0 + ((lane >> 3) & 1);
                unsigned ad = baseB + swzoff(row, ch);
                unsigned r0, r1, r2, r3;
                asm volatile("ldmatrix.sync.aligned.m8n8.x4.shared.b16 {%0,%1,%2,%3}, [%4];"
                    : "=r"(r0), "=r"(r1), "=r"(r2), "=r"(r3) : "r"(ad));
                b[2*p][0] = r0; b[2*p][1] = r1; b[2*p+1][0] = r2; b[2*p+1][1] = r3;
            }
#pragma unroll
            for (int mt = 0; mt < 4; mt++)
#pragma unroll
                for (int nt = 0; nt < 4; nt++)
                    asm volatile("mma.sync.aligned.m16n8k16.row.col.f32.bf16.bf16.f32 "
                        "{%0,%1,%2,%3}, {%4,%5,%6,%7}, {%8,%9}, {%0,%1,%2,%3};"
                        : "+f"(acc[mt][nt][0]), "+f"(acc[mt][nt][1]),
                          "+f"(acc[mt][nt][2]), "+f"(acc[mt][nt][3])
                        : "r"(a[mt][0]), "r"(a[mt][1]), "r"(a[mt][2]), "r"(a[mt][3]),
                          "r"(b[nt][0]), "r"(b[nt][1]));
        }
    }

    // epilogue
#pragma unroll
    for (int mt = 0; mt < 4; mt++) {
        int grow = bm + wm*64 + mt*16 + (lane >> 2);
#pragma unroll
        for (int nt = 0; nt < 4; nt++) {
            int gcol = bn + wn*32 + nt*8 + 2*(lane & 3);
            if (gcol < N) {
                float2* p0 = (float2*)&C[(size_t)grow*ldc + gcol];
                float2* p1 = (float2*)&C[(size_t)(grow+8)*ldc + gcol];
                float2 v0 = make_float2(acc[mt][nt][0], acc[mt][nt][1]);
                float2 v1 = make_float2(acc[mt][nt][2], acc[mt][nt][3]);
                if (ACC) {
                    float2 o0 = *p0, o1 = *p1;
                    v0.x += o0.x; v0.y += o0.y; v1.x += o1.x; v1.y += o1.y;
                }
                *p0 = v0; *p1 = v1;
            }
        }
    }
}

// ---------------- flash attention (vectorized smem access); writes bf16 split A3 ----------------
__global__ __launch_bounds__(256)
void attn_kernel(const float* __restrict__ q, const float* __restrict__ k,
                 const float* __restrict__ v, int ldv, const int* __restrict__ ids,
                 __nv_bfloat16* __restrict__ a3)
{
    __shared__ __align__(16) float QT[64][68];   // [d][r], row stride 272B (16B mult)
    __shared__ __align__(16) float KT[64][34];   // [d][c], row stride 136B (8B mult)
    __shared__ __align__(16) float Ps[32][68];   // [c][r]
    __shared__ __align__(16) float Vs[32][64];   // [c][d]
    __shared__ float pads[32];

    const int b  = blockIdx.z, h = blockIdx.y, q0 = blockIdx.x * 64;
    const int tid = threadIdx.x;
    const int sx = tid & 15, sy = tid >> 4;
    const size_t hoff = (size_t)h * HDD;

    for (int i2 = tid; i2 < 64*64; i2 += 256) {
        int r = i2 >> 6, d = i2 & 63;
        QT[d][r] = q[((size_t)(b*SS + q0 + r))*HH + hoff + d];
    }
    float m[4], l[4], o[4][4];
#pragma unroll
    for (int i = 0; i < 4; i++) {
        m[i] = -3e38f; l[i] = 0.f;
#pragma unroll
        for (int j = 0; j < 4; j++) o[i][j] = 0.f;
    }
    __syncthreads();

    const int nk = q0 + 64;
    for (int c0 = 0; c0 < nk; c0 += 32) {
        // load K tile, V tile, pad mask together
        for (int i2 = tid; i2 < 32*64; i2 += 256) {
            int c = i2 >> 6, d = i2 & 63;
            size_t rowb = (size_t)(b*SS + c0 + c);
            KT[d][c] = k[rowb*HH + hoff + d];
            Vs[c][d] = v[rowb*ldv + hoff + d];
        }
        if (tid < 32)
            pads[tid] = (ids[b*SS + c0 + tid] != 0) ? 0.f : -10000.f;
        __syncthreads();

        // scores: rows sy*4+i, cols sx*2+j  (vector loads: 1x LDS.128 + 1x LDS.64 per d)
        float sv[4][2];
#pragma unroll
        for (int i = 0; i < 4; i++) { sv[i][0] = 0.f; sv[i][1] = 0.f; }
#pragma unroll 4
        for (int d = 0; d < 64; d++) {
            float4 qa = *(const float4*)&QT[d][sy*4];
            float2 kb = *(const float2*)&KT[d][sx*2];
            sv[0][0] += qa.x*kb.x; sv[0][1] += qa.x*kb.y;
            sv[1][0] += qa.y*kb.x; sv[1][1] += qa.y*kb.y;
            sv[2][0] += qa.z*kb.x; sv[2][1] += qa.z*kb.y;
            sv[3][0] += qa.w*kb.x; sv[3][1] += qa.w*kb.y;
        }

        float corr[4];
#pragma unroll
        for (int i = 0; i < 4; i++) {
            int qrow = q0 + sy*4 + i;
#pragma unroll
            for (int j = 0; j < 2; j++) {
                int cc = c0 + sx*2 + j;
                float s_ = sv[i][j]*0.125f + pads[sx*2+j];
                if (cc > qrow) s_ = -3e38f;
                sv[i][j] = s_;
            }
            float tmax = fmaxf(sv[i][0], sv[i][1]);
#pragma unroll
            for (int off = 8; off > 0; off >>= 1)
                tmax = fmaxf(tmax, __shfl_xor_sync(0xffffffffu, tmax, off));
            float mn = fmaxf(m[i], tmax);
            corr[i] = expf(m[i] - mn);
            m[i] = mn;
            float p0 = expf(sv[i][0] - mn);
            float p1 = expf(sv[i][1] - mn);
            float rs = p0 + p1;
#pragma unroll
            for (int off = 8; off > 0; off >>= 1)
                rs += __shfl_xor_sync(0xffffffffu, rs, off);
            l[i] = l[i]*corr[i] + rs;
            Ps[sx*2+0][sy*4+i] = p0;
            Ps[sx*2+1][sy*4+i] = p1;
#pragma unroll
            for (int j = 0; j < 4; j++) o[i][j] *= corr[i];
        }
        __syncthreads();

        // P.V  (vector loads: 2x LDS.128 per key)
#pragma unroll 4
        for (int c = 0; c < 32; c++) {
            float4 pv = *(const float4*)&Ps[c][sy*4];
            float4 vv = *(const float4*)&Vs[c][sx*4];
            o[0][0] += pv.x*vv.x; o[0][1] += pv.x*vv.y; o[0][2] += pv.x*vv.z; o[0][3] += pv.x*vv.w;
            o[1][0] += pv.y*vv.x; o[1][1] += pv.y*vv.y; o[1][2] += pv.y*vv.z; o[1][3] += pv.y*vv.w;
            o[2][0] += pv.z*vv.x; o[2][1] += pv.z*vv.y; o[2][2] += pv.z*vv.z; o[2][3] += pv.z*vv.w;
            o[3][0] += pv.w*vv.x; o[3][1] += pv.w*vv.y; o[3][2] += pv.w*vv.z; o[3][3] += pv.w*vv.w;
        }
        __syncthreads();
    }

#pragma unroll
    for (int i = 0; i < 4; i++) {
        float inv = 1.f / l[i];
        size_t arow = (size_t)(b*SS + q0 + sy*4 + i) * 3072 + hoff + sx*4;
#pragma unroll
        for (int e = 0; e < 4; e++) {
            float y = o[i][e] * inv;
            __nv_bfloat16 hh = __float2bfloat16(y);
            __nv_bfloat16 ll = __float2bfloat16(y - __bfloat162float(hh));
            a3[arow + e]        = hh;
            a3[arow + 1024 + e] = ll;
            a3[arow + 2048 + e] = hh;
        }
    }
}

// ---------------- launch ----------------
extern "C" void kernel_launch(void* const* d_in, const int* in_sizes, int n_in,
                              void* d_out, int out_size)
{
    if (n_in != 15) return;
    const int expect[15] = {
        MM, VV*HH,
        LL*HH*HH, LL*HH*HH, LL*HH*HH, LL*HH*HH,
        LL*HH*II, LL*HH*II, LL*II*HH,
        LL*HH, LL*HH, LL*HH, LL*HH,
        HH, HH
    };
    for (int i = 0; i < 15; i++)
        if (in_sizes[i] != expect[i]) return;

    const int*   ids    = (const int*)  d_in[0];
    const float* emb    = (const float*)d_in[1];
    const float* q_w    = (const float*)d_in[2];
    const float* k_w    = (const float*)d_in[3];
    const float* v_w    = (const float*)d_in[4];
    const float* o_w    = (const float*)d_in[5];
    const float* gate_w = (const float*)d_in[6];
    const float* up_w   = (const float*)d_in[7];
    const float* down_w = (const float*)d_in[8];
    const float* ln1_w  = (const float*)d_in[9];
    const float* ln1_b  = (const float*)d_in[10];
    const float* ln2_w  = (const float*)d_in[11];
    const float* ln2_b  = (const float*)d_in[12];
    const float* lnf_w  = (const float*)d_in[13];
    const float* lnf_b  = (const float*)d_in[14];
    float* out = (float*)d_out;

    float *px, *pqkv, *pq2, *pk2, *pgu;
    __nv_bfloat16 *pa3, *pg3, *pb3, *pe3;
    cudaGetSymbolAddress((void**)&px,   g_x);
    cudaGetSymbolAddress((void**)&pqkv, g_qkv);
    cudaGetSymbolAddress((void**)&pq2,  g_q2);
    cudaGetSymbolAddress((void**)&pk2,  g_k2);
    cudaGetSymbolAddress((void**)&pgu,  g_gu);
    cudaGetSymbolAddress((void**)&pa3,  g_a3);
    cudaGetSymbolAddress((void**)&pg3,  g_g3);
    cudaGetSymbolAddress((void**)&pb3,  g_b3);
    cudaGetSymbolAddress((void**)&pe3,  g_e3);

    embed_kernel<<<(MM*HH + 255)/256, 256>>>(ids, emb, px);
    split_emb<<<(VV*HH + 255)/256, 256>>>(emb, pe3);

    const int TWQ  = HH*HH;
    const int TWD  = HH*II;

    dim3 go(8, 32);                // N=1024
    dim3 ggu(44, 32);              // N=5632
    dim3 glog(250, 32);            // N=32000
    dim3 gattn(SS/64, NHH, BB);
    dim3 gsilu((II + 255)/256, MM);

    for (int l = 0; l < LL; l++) {
        const float* qw = q_w    + (size_t)l*HH*HH;
        const float* kw = k_w    + (size_t)l*HH*HH;
        const float* vw = v_w    + (size_t)l*HH*HH;
        const float* ow = o_w    + (size_t)l*HH*HH;
        const float* gw = gate_w + (size_t)l*HH*II;
        const float* uw = up_w   + (size_t)l*HH*II;
        const float* dw = down_w + (size_t)l*II*HH;

        ln_split_kernel<<<MM, 256>>>(px, ln1_w + l*HH, ln1_b + l*HH, pa3);
        split_w_qkv<<<(3072*1024+255)/256, 256>>>(qw, kw, vw, pb3);

        bgemm<<<go, 256>>>(pa3, 3072, pb3,                     3072, pqkv,        3072, HH, 3072, 0);
        bgemm<<<go, 256>>>(pa3, 3072, pb3 + (size_t)1024*3072, 3072, pqkv + 1024, 3072, HH, 3072, 0);
        bgemm<<<go, 256>>>(pa3, 3072, pb3 + (size_t)2048*3072, 3072, pqkv + 2048, 3072, HH, 3072, 0);

        rope2_kernel<<<MM, 512>>>(pqkv, pq2, pk2);
        attn_kernel<<<gattn, 256>>>(pq2, pk2, pqkv + 2048, 3072, ids, pa3);

        split_w<<<(TWQ+255)/256, 256>>>(ow, HH, HH, HH, pb3, 3072, TWQ);
        bgemm<<<go, 256>>>(pa3, 3072, pb3, 3072, px, HH, HH, 3072, 1);

        ln_split_kernel<<<MM, 256>>>(px, ln2_w + l*HH, ln2_b + l*HH, pa3);

        split_w_gu<<<(5632*1024+255)/256, 256>>>(gw, uw, pb3);
        bgemm<<<ggu, 256>>>(pa3, 3072, pb3, 3072, pgu, 5632, 5632, 3072, 0);

        silu_split_kernel<<<gsilu, 256>>>(pgu, pg3);

        split_w<<<(TWD+255)/256, 256>>>(dw, II, HH, HH, pb3, 8192, TWD);
        bgemm<<<go, 256>>>(pg3, 8192, pb3, 8192, px, HH, HH, 8192, 1);
    }

    ln_split_kernel<<<MM, 256>>>(px, lnf_w, lnf_b, pa3);
    bgemm<<<glog, 256>>>(pa3, 3072, pe3, 3072, out, VV, VV, 3072, 0);
}

// round 16
// speedup vs baseline: 1.0829x; 1.0172x over previous
#include <cuda_runtime.h>
#include <cuda_bf16.h>
#include <math.h>
#include <stdint.h>

// ---------------- problem constants ----------------
#define BB   2
#define SS   2048
#define HH   1024
#define NHH  16
#define HDD  64
#define LL   8
#define VV   32000
#define II   2730
#define MM   (BB*SS)

// ---------------- device scratch ----------------
__device__ float g_x  [MM*HH];
__device__ float g_qkv[(size_t)MM*3072];
__device__ float g_q2 [MM*HH];
__device__ float g_k2 [MM*HH];
__device__ float g_gu [(size_t)MM*5632];

// bf16 split buffers (A3 = [hi|lo|hi], B3 = [hi|hi|lo] along K)
__device__ __nv_bfloat16 g_a3[(size_t)MM*3072];
__device__ __nv_bfloat16 g_g3[(size_t)MM*8192];
__device__ __nv_bfloat16 g_b3[(size_t)5632*3072];
__device__ __nv_bfloat16 g_e3[(size_t)VV*3072];

// ---------------- embedding gather ----------------
__global__ void embed_kernel(const int* __restrict__ ids,
                             const float* __restrict__ emb,
                             float* __restrict__ x)
{
    int idx = blockIdx.x * blockDim.x + threadIdx.x;
    if (idx >= MM*HH) return;
    int m = idx >> 10;
    int d = idx & 1023;
    x[idx] = emb[(size_t)ids[m] * HH + d];
}

// ---------------- layernorm fused with bf16 split: writes A3 [hi|lo|hi] ----------------
__global__ void ln_split_kernel(const float* __restrict__ x,
                                const float* __restrict__ w,
                                const float* __restrict__ b,
                                __nv_bfloat16* __restrict__ a3)
{
    int row = blockIdx.x;
    const float* xr = x + (size_t)row * HH;
    float v[4], s = 0.f, sq = 0.f;
#pragma unroll
    for (int i = 0; i < 4; i++) {
        v[i] = xr[threadIdx.x + i*256];
        s  += v[i];
        sq += v[i]*v[i];
    }
    __shared__ float rs[8], rq[8];
    int lane = threadIdx.x & 31, wid = threadIdx.x >> 5;
#pragma unroll
    for (int off = 16; off > 0; off >>= 1) {
        s  += __shfl_xor_sync(0xffffffffu, s,  off);
        sq += __shfl_xor_sync(0xffffffffu, sq, off);
    }
    if (lane == 0) { rs[wid] = s; rq[wid] = sq; }
    __syncthreads();
    if (threadIdx.x == 0) {
        float ts = 0.f, tq = 0.f;
        for (int i = 0; i < 8; i++) { ts += rs[i]; tq += rq[i]; }
        rs[0] = ts; rq[0] = tq;
    }
    __syncthreads();
    float mu  = rs[0] * (1.f/HH);
    float var = rq[0] * (1.f/HH) - mu*mu;
    float inv = rsqrtf(var + 1e-5f);
    __nv_bfloat16* arow = a3 + (size_t)row * 3072;
#pragma unroll
    for (int i = 0; i < 4; i++) {
        int d = threadIdx.x + i*256;
        float y = (v[i] - mu) * inv * w[d] + b[d];
        __nv_bfloat16 h = __float2bfloat16(y);
        __nv_bfloat16 l = __float2bfloat16(y - __bfloat162float(h));
        arow[d]        = h;
        arow[1024 + d] = l;
        arow[2048 + d] = h;
    }
}

// ---------------- RoPE v2 (proven correct), reads fused qkv ----------------
__global__ __launch_bounds__(512)
void rope2_kernel(const float* __restrict__ qkv,
                  float* __restrict__ qout, float* __restrict__ kout)
{
    const int m = blockIdx.x;
    const int t = threadIdx.x;
    const int head = t >> 5;
    const int i    = t & 31;
    const int s    = m % SS;

    const float LOG1E4_OVER_32 = 0.28782313662425f;
    float invf = expf(-(float)i * LOG1E4_OVER_32);
    float ang  = (float)s * invf;
    float c  = cosf(ang);
    float sn = sinf(ang);

    size_t inb  = (size_t)m * 3072 + head * HDD + i;
    size_t outb = (size_t)m * HH   + head * HDD + i;
    float qa = qkv[inb], qb = qkv[inb + 32];
    qout[outb]      = fmaf(qa, c, -qb * sn);
    qout[outb + 32] = fmaf(qb, c,  qa * sn);
    float ka = qkv[inb + 1024], kb = qkv[inb + 1024 + 32];
    kout[outb]      = fmaf(ka, c, -kb * sn);
    kout[outb + 32] = fmaf(kb, c,  ka * sn);
}

// ---------------- SiLU(gate)*up fused with bf16 split: writes G3 [hi|lo|hi] ----------------
__global__ void silu_split_kernel(const float* __restrict__ gu,
                                  __nv_bfloat16* __restrict__ g3)
{
    int c = blockIdx.x * blockDim.x + threadIdx.x;
    int m = blockIdx.y;
    if (c >= II) return;
    size_t a = (size_t)m * 5632 + c;
    float x = gu[a];
    float y = x / (1.f + expf(-x)) * gu[a + 2816];
    __nv_bfloat16 h = __float2bfloat16(y);
    __nv_bfloat16 l = __float2bfloat16(y - __bfloat162float(h));
    size_t base = (size_t)m * 8192;
    g3[base + c]          = h;
    g3[base + 2730 + c]   = l;
    g3[base + 5460 + c]   = h;
    if (c < 2) g3[base + 8190 + c] = __float2bfloat16(0.f);
}

// ---------------- weight conversions ----------------
__global__ void split_w_qkv(const float* __restrict__ qw, const float* __restrict__ kw,
                            const float* __restrict__ vw, __nv_bfloat16* __restrict__ B3)
{
    int idx = blockIdx.x*256 + threadIdx.x;
    if (idx >= 3072*1024) return;
    int n = idx >> 10, k = idx & 1023;
    const float* W = (n < 1024) ? qw : ((n < 2048) ? kw : vw);
    int nn = n & 1023;
    float x = W[(size_t)k*1024 + nn];
    __nv_bfloat16 h = __float2bfloat16(x);
    __nv_bfloat16 l = __float2bfloat16(x - __bfloat162float(h));
    size_t base = (size_t)n*3072;
    B3[base + k]        = h;
    B3[base + 1024 + k] = h;
    B3[base + 2048 + k] = l;
}

__global__ void split_w_gu(const float* __restrict__ gw, const float* __restrict__ uw,
                           __nv_bfloat16* __restrict__ B3)
{
    int idx = blockIdx.x*256 + threadIdx.x;
    if (idx >= 5632*1024) return;
    int n = idx >> 10, k = idx & 1023;
    const float* W = (n < 2816) ? gw : uw;
    int nn = (n < 2816) ? n : (n - 2816);
    float x = (nn < II) ? W[(size_t)k*II + nn] : 0.f;
    __nv_bfloat16 h = __float2bfloat16(x);
    __nv_bfloat16 l = __float2bfloat16(x - __bfloat162float(h));
    size_t base = (size_t)n*3072;
    B3[base + k]        = h;
    B3[base + 1024 + k] = h;
    B3[base + 2048 + k] = l;
}

__global__ void split_w(const float* __restrict__ W, int K, int N, int Npad,
                        __nv_bfloat16* __restrict__ B3, int ld3, int total)
{
    int idx = blockIdx.x*256 + threadIdx.x;
    if (idx >= total) return;
    int n = idx / K, k = idx - n*K;
    float x = (n < N) ? W[(size_t)k*N + n] : 0.f;
    __nv_bfloat16 h = __float2bfloat16(x);
    __nv_bfloat16 l = __float2bfloat16(x - __bfloat162float(h));
    size_t base = (size_t)n*ld3;
    B3[base + k]       = h;
    B3[base + K + k]   = h;
    B3[base + 2*K + k] = l;
    int pad = ld3 - 3*K;
    if (k < pad) B3[base + 3*K + k] = __float2bfloat16(0.f);
}

__global__ void split_emb(const float* __restrict__ E, __nv_bfloat16* __restrict__ E3)
{
    int idx = blockIdx.x*256 + threadIdx.x;
    if (idx >= VV*HH) return;
    int n = idx >> 10, k = idx & 1023;
    float x = E[idx];
    __nv_bfloat16 h = __float2bfloat16(x);
    __nv_bfloat16 l = __float2bfloat16(x - __bfloat162float(h));
    size_t base = (size_t)n*3072;
    E3[base + k]        = h;
    E3[base + 1024 + k] = h;
    E3[base + 2048 + k] = l;
}

// ---------------- tensor-core GEMM: 128x128x32, 4 warps of 64x64, 3-stage ----------------
__device__ __forceinline__ unsigned swzoff(int row, int ch)
{
    return (unsigned)(row*64 + ((ch ^ ((row>>1)&3)) << 4));
}

__global__ __launch_bounds__(128, 2)
void bgemm(const __nv_bfloat16* __restrict__ A3, int lda,
           const __nv_bfloat16* __restrict__ B3, int ldb,
           float* __restrict__ C, int ldc,
           int N, int K3, int ACC)
{
    __shared__ __align__(16) __nv_bfloat16 smA[3][128*32];
    __shared__ __align__(16) __nv_bfloat16 smB[3][128*32];

    const int tid  = threadIdx.x;
    const int lane = tid & 31, warp = tid >> 5;       // 4 warps
    const int wm = warp >> 1, wn = warp & 1;          // 2x2 warp grid, 64x64 tiles
    const int bm = blockIdx.y * 128, bn = blockIdx.x * 128;

    const unsigned sA0 = (unsigned)__cvta_generic_to_shared(&smA[0][0]);
    const unsigned sB0 = (unsigned)__cvta_generic_to_shared(&smB[0][0]);

    float acc[4][8][4];
#pragma unroll
    for (int i = 0; i < 4; i++)
#pragma unroll
        for (int j = 0; j < 8; j++)
#pragma unroll
            for (int r = 0; r < 4; r++) acc[i][j][r] = 0.f;

    const int S = K3 >> 5;

    auto issue = [&](int s) {
        const int buf = s % 3;
        const int k0  = s << 5;
#pragma unroll
        for (int i = 0; i < 4; i++) {
            int idx = i*128 + tid;                     // 0..511
            int row = idx >> 2, ch = idx & 3;
            unsigned so = (unsigned)(buf*8192) + swzoff(row, ch);
            const __nv_bfloat16* ga = A3 + (size_t)(bm+row)*lda + k0 + ch*8;
            asm volatile("cp.async.cg.shared.global [%0], [%1], 16;\n" :: "r"(sA0+so), "l"(ga));
            const __nv_bfloat16* gb = B3 + (size_t)(bn+row)*ldb + k0 + ch*8;
            asm volatile("cp.async.cg.shared.global [%0], [%1], 16;\n" :: "r"(sB0+so), "l"(gb));
        }
        asm volatile("cp.async.commit_group;\n" ::);
    };

    issue(0); issue(1);

    for (int s = 0; s < S; s++) {
        if (s + 1 < S) asm volatile("cp.async.wait_group 1;\n" ::);
        else           asm volatile("cp.async.wait_group 0;\n" ::);
        __syncthreads();
        if (s + 2 < S) issue(s + 2);

        const int buf = s % 3;
        const unsigned baseA = sA0 + (unsigned)(buf*8192);
        const unsigned baseB = sB0 + (unsigned)(buf*8192);
#pragma unroll
        for (int ks = 0; ks < 2; ks++) {
            const int c0 = ks*2;
            unsigned a[4][4], b[8][2];
#pragma unroll
            for (int mt = 0; mt < 4; mt++) {
                int row = wm*64 + mt*16 + (lane & 7) + ((lane >> 3) & 1)*8;
                int ch  = c0 + (lane >> 4);
                unsigned ad = baseA + swzoff(row, ch);
                asm volatile("ldmatrix.sync.aligned.m8n8.x4.shared.b16 {%0,%1,%2,%3}, [%4];"
                    : "=r"(a[mt][0]), "=r"(a[mt][1]), "=r"(a[mt][2]), "=r"(a[mt][3]) : "r"(ad));
            }
#pragma unroll
            for (int p = 0; p < 4; p++) {
                int row = wn*64 + p*16 + (lane & 7) + ((lane >> 4) & 1)*8;
                int ch  = c0 + ((lane >> 3) & 1);
                unsigned ad = baseB + swzoff(row, ch);
                unsigned r0, r1, r2, r3;
                asm volatile("ldmatrix.sync.aligned.m8n8.x4.shared.b16 {%0,%1,%2,%3}, [%4];"
                    : "=r"(r0), "=r"(r1), "=r"(r2), "=r"(r3) : "r"(ad));
                b[2*p][0] = r0; b[2*p][1] = r1; b[2*p+1][0] = r2; b[2*p+1][1] = r3;
            }
#pragma unroll
            for (int mt = 0; mt < 4; mt++)
#pragma unroll
                for (int nt = 0; nt < 8; nt++)
                    asm volatile("mma.sync.aligned.m16n8k16.row.col.f32.bf16.bf16.f32 "
                        "{%0,%1,%2,%3}, {%4,%5,%6,%7}, {%8,%9}, {%0,%1,%2,%3};"
                        : "+f"(acc[mt][nt][0]), "+f"(acc[mt][nt][1]),
                          "+f"(acc[mt][nt][2]), "+f"(acc[mt][nt][3])
                        : "r"(a[mt][0]), "r"(a[mt][1]), "r"(a[mt][2]), "r"(a[mt][3]),
                          "r"(b[nt][0]), "r"(b[nt][1]));
        }
    }

    // epilogue
#pragma unroll
    for (int mt = 0; mt < 4; mt++) {
        int grow = bm + wm*64 + mt*16 + (lane >> 2);
#pragma unroll
        for (int nt = 0; nt < 8; nt++) {
            int gcol = bn + wn*64 + nt*8 + 2*(lane & 3);
            if (gcol < N) {
                float2* p0 = (float2*)&C[(size_t)grow*ldc + gcol];
                float2* p1 = (float2*)&C[(size_t)(grow+8)*ldc + gcol];
                float2 v0 = make_float2(acc[mt][nt][0], acc[mt][nt][1]);
                float2 v1 = make_float2(acc[mt][nt][2], acc[mt][nt][3]);
                if (ACC) {
                    float2 o0 = *p0, o1 = *p1;
                    v0.x += o0.x; v0.y += o0.y; v1.x += o1.x; v1.y += o1.y;
                }
                *p0 = v0; *p1 = v1;
            }
        }
    }
}

// ---------------- flash attention (vectorized; longest-first order); writes bf16 split A3 ----------------
__global__ __launch_bounds__(256)
void attn_kernel(const float* __restrict__ q, const float* __restrict__ k,
                 const float* __restrict__ v, int ldv, const int* __restrict__ ids,
                 __nv_bfloat16* __restrict__ a3)
{
    __shared__ __align__(16) float QT[64][68];
    __shared__ __align__(16) float KT[64][34];
    __shared__ __align__(16) float Ps[32][68];
    __shared__ __align__(16) float Vs[32][64];
    __shared__ float pads[32];

    const int b  = blockIdx.z, h = blockIdx.y;
    const int q0 = (gridDim.x - 1 - blockIdx.x) * 64;   // longest blocks first
    const int tid = threadIdx.x;
    const int sx = tid & 15, sy = tid >> 4;
    const size_t hoff = (size_t)h * HDD;

    for (int i2 = tid; i2 < 64*64; i2 += 256) {
        int r = i2 >> 6, d = i2 & 63;
        QT[d][r] = q[((size_t)(b*SS + q0 + r))*HH + hoff + d];
    }
    float m[4], l[4], o[4][4];
#pragma unroll
    for (int i = 0; i < 4; i++) {
        m[i] = -3e38f; l[i] = 0.f;
#pragma unroll
        for (int j = 0; j < 4; j++) o[i][j] = 0.f;
    }
    __syncthreads();

    const int nk = q0 + 64;
    for (int c0 = 0; c0 < nk; c0 += 32) {
        for (int i2 = tid; i2 < 32*64; i2 += 256) {
            int c = i2 >> 6, d = i2 & 63;
            size_t rowb = (size_t)(b*SS + c0 + c);
            KT[d][c] = k[rowb*HH + hoff + d];
            Vs[c][d] = v[rowb*ldv + hoff + d];
        }
        if (tid < 32)
            pads[tid] = (ids[b*SS + c0 + tid] != 0) ? 0.f : -10000.f;
        __syncthreads();

        float sv[4][2];
#pragma unroll
        for (int i = 0; i < 4; i++) { sv[i][0] = 0.f; sv[i][1] = 0.f; }
#pragma unroll 4
        for (int d = 0; d < 64; d++) {
            float4 qa = *(const float4*)&QT[d][sy*4];
            float2 kb = *(const float2*)&KT[d][sx*2];
            sv[0][0] += qa.x*kb.x; sv[0][1] += qa.x*kb.y;
            sv[1][0] += qa.y*kb.x; sv[1][1] += qa.y*kb.y;
            sv[2][0] += qa.z*kb.x; sv[2][1] += qa.z*kb.y;
            sv[3][0] += qa.w*kb.x; sv[3][1] += qa.w*kb.y;
        }

        float corr[4];
#pragma unroll
        for (int i = 0; i < 4; i++) {
            int qrow = q0 + sy*4 + i;
#pragma unroll
            for (int j = 0; j < 2; j++) {
                int cc = c0 + sx*2 + j;
                float s_ = sv[i][j]*0.125f + pads[sx*2+j];
                if (cc > qrow) s_ = -3e38f;
                sv[i][j] = s_;
            }
            float tmax = fmaxf(sv[i][0], sv[i][1]);
#pragma unroll
            for (int off = 8; off > 0; off >>= 1)
                tmax = fmaxf(tmax, __shfl_xor_sync(0xffffffffu, tmax, off));
            float mn = fmaxf(m[i], tmax);
            corr[i] = expf(m[i] - mn);
            m[i] = mn;
            float p0 = expf(sv[i][0] - mn);
            float p1 = expf(sv[i][1] - mn);
            float rs = p0 + p1;
#pragma unroll
            for (int off = 8; off > 0; off >>= 1)
                rs += __shfl_xor_sync(0xffffffffu, rs, off);
            l[i] = l[i]*corr[i] + rs;
            Ps[sx*2+0][sy*4+i] = p0;
            Ps[sx*2+1][sy*4+i] = p1;
#pragma unroll
            for (int j = 0; j < 4; j++) o[i][j] *= corr[i];
        }
        __syncthreads();

#pragma unroll 4
        for (int c = 0; c < 32; c++) {
            float4 pv = *(const float4*)&Ps[c][sy*4];
            float4 vv = *(const float4*)&Vs[c][sx*4];
            o[0][0] += pv.x*vv.x; o[0][1] += pv.x*vv.y; o[0][2] += pv.x*vv.z; o[0][3] += pv.x*vv.w;
            o[1][0] += pv.y*vv.x; o[1][1] += pv.y*vv.y; o[1][2] += pv.y*vv.z; o[1][3] += pv.y*vv.w;
            o[2][0] += pv.z*vv.x; o[2][1] += pv.z*vv.y; o[2][2] += pv.z*vv.z; o[2][3] += pv.z*vv.w;
            o[3][0] += pv.w*vv.x; o[3][1] += pv.w*vv.y; o[3][2] += pv.w*vv.z; o[3][3] += pv.w*vv.w;
        }
        __syncthreads();
    }

#pragma unroll
    for (int i = 0; i < 4; i++) {
        float inv = 1.f / l[i];
        size_t arow = (size_t)(b*SS + q0 + sy*4 + i) * 3072 + hoff + sx*4;
#pragma unroll
        for (int e = 0; e < 4; e++) {
            float y = o[i][e] * inv;
            __nv_bfloat16 hh = __float2bfloat16(y);
            __nv_bfloat16 ll = __float2bfloat16(y - __bfloat162float(hh));
            a3[arow + e]        = hh;
            a3[arow + 1024 + e] = ll;
            a3[arow + 2048 + e] = hh;
        }
    }
}

// ---------------- launch ----------------
extern "C" void kernel_launch(void* const* d_in, const int* in_sizes, int n_in,
                              void* d_out, int out_size)
{
    if (n_in != 15) return;
    const int expect[15] = {
        MM, VV*HH,
        LL*HH*HH, LL*HH*HH, LL*HH*HH, LL*HH*HH,
        LL*HH*II, LL*HH*II, LL*II*HH,
        LL*HH, LL*HH, LL*HH, LL*HH,
        HH, HH
    };
    for (int i = 0; i < 15; i++)
        if (in_sizes[i] != expect[i]) return;

    const int*   ids    = (const int*)  d_in[0];
    const float* emb    = (const float*)d_in[1];
    const float* q_w    = (const float*)d_in[2];
    const float* k_w    = (const float*)d_in[3];
    const float* v_w    = (const float*)d_in[4];
    const float* o_w    = (const float*)d_in[5];
    const float* gate_w = (const float*)d_in[6];
    const float* up_w   = (const float*)d_in[7];
    const float* down_w = (const float*)d_in[8];
    const float* ln1_w  = (const float*)d_in[9];
    const float* ln1_b  = (const float*)d_in[10];
    const float* ln2_w  = (const float*)d_in[11];
    const float* ln2_b  = (const float*)d_in[12];
    const float* lnf_w  = (const float*)d_in[13];
    const float* lnf_b  = (const float*)d_in[14];
    float* out = (float*)d_out;

    float *px, *pqkv, *pq2, *pk2, *pgu;
    __nv_bfloat16 *pa3, *pg3, *pb3, *pe3;
    cudaGetSymbolAddress((void**)&px,   g_x);
    cudaGetSymbolAddress((void**)&pqkv, g_qkv);
    cudaGetSymbolAddress((void**)&pq2,  g_q2);
    cudaGetSymbolAddress((void**)&pk2,  g_k2);
    cudaGetSymbolAddress((void**)&pgu,  g_gu);
    cudaGetSymbolAddress((void**)&pa3,  g_a3);
    cudaGetSymbolAddress((void**)&pg3,  g_g3);
    cudaGetSymbolAddress((void**)&pb3,  g_b3);
    cudaGetSymbolAddress((void**)&pe3,  g_e3);

    embed_kernel<<<(MM*HH + 255)/256, 256>>>(ids, emb, px);
    split_emb<<<(VV*HH + 255)/256, 256>>>(emb, pe3);

    const int TWQ  = HH*HH;
    const int TWD  = HH*II;

    dim3 go(8, 32);                // N=1024
    dim3 ggu(44, 32);              // N=5632
    dim3 glog(250, 32);            // N=32000
    dim3 gattn(SS/64, NHH, BB);
    dim3 gsilu((II + 255)/256, MM);

    for (int l = 0; l < LL; l++) {
        const float* qw = q_w    + (size_t)l*HH*HH;
        const float* kw = k_w    + (size_t)l*HH*HH;
        const float* vw = v_w    + (size_t)l*HH*HH;
        const float* ow = o_w    + (size_t)l*HH*HH;
        const float* gw = gate_w + (size_t)l*HH*II;
        const float* uw = up_w   + (size_t)l*HH*II;
        const float* dw = down_w + (size_t)l*II*HH;

        ln_split_kernel<<<MM, 256>>>(px, ln1_w + l*HH, ln1_b + l*HH, pa3);
        split_w_qkv<<<(3072*1024+255)/256, 256>>>(qw, kw, vw, pb3);

        bgemm<<<go, 128>>>(pa3, 3072, pb3,                     3072, pqkv,        3072, HH, 3072, 0);
        bgemm<<<go, 128>>>(pa3, 3072, pb3 + (size_t)1024*3072, 3072, pqkv + 1024, 3072, HH, 3072, 0);
        bgemm<<<go, 128>>>(pa3, 3072, pb3 + (size_t)2048*3072, 3072, pqkv + 2048, 3072, HH, 3072, 0);

        rope2_kernel<<<MM, 512>>>(pqkv, pq2, pk2);
        attn_kernel<<<gattn, 256>>>(pq2, pk2, pqkv + 2048, 3072, ids, pa3);

        split_w<<<(TWQ+255)/256, 256>>>(ow, HH, HH, HH, pb3, 3072, TWQ);
        bgemm<<<go, 128>>>(pa3, 3072, pb3, 3072, px, HH, HH, 3072, 1);

        ln_split_kernel<<<MM, 256>>>(px, ln2_w + l*HH, ln2_b + l*HH, pa3);

        split_w_gu<<<(5632*1024+255)/256, 256>>>(gw, uw, pb3);
        bgemm<<<ggu, 128>>>(pa3, 3072, pb3, 3072, pgu, 5632, 5632, 3072, 0);

        silu_split_kernel<<<gsilu, 256>>>(pgu, pg3);

        split_w<<<(TWD+255)/256, 256>>>(dw, II, HH, HH, pb3, 8192, TWD);
        bgemm<<<go, 128>>>(pg3, 8192, pb3, 8192, px, HH, HH, 8192, 1);
    }

    ln_split_kernel<<<MM, 256>>>(px, lnf_w, lnf_b, pa3);
    bgemm<<<glog, 128>>>(pa3, 3072, pe3, 3072, out, VV, VV, 3072, 0);
}